// round 4
// baseline (speedup 1.0000x reference)
#include <cuda_runtime.h>

#define NN 50000
#define NE 320000
#define HID 256
#define NLAYERS 5
#define BN_EPS 1e-5f

// ---------------- scratch (device globals; no allocation allowed) -------------
__device__ float g_h[(size_t)NN * HID];     // h after BN (layer output)
__device__ float g_agg[(size_t)NN * HID];   // aggregation result
__device__ float g_tmp[(size_t)NN * HID];   // pre-BN activations
__device__ float g_dinv[NN];
__device__ int   g_degi[NN];
__device__ int   g_off[NN + 1];
__device__ int   g_cur[NN];
__device__ int   g_row[NE];    // CSR-ordered source node per slot
__device__ float g_nrm[NE];    // CSR-ordered norm per slot
__device__ float g_S[(size_t)NN * 4];  // per-node sum norm*ea (layer-invariant)
__device__ float g_cs[HID];
__device__ float g_cs2[HID];
__device__ int   g_is64;       // 1 if edge_index buffer is int64, 0 if int32

// ---------------- edge-index dtype detection ----------------------------------
// int64 [2,NE] with values < 2^31: every odd 32-bit word is 0.
// int32 [2,NE] with ~random ids in [0,50000): odd words are almost surely nonzero.
__global__ void detect_kernel(const int* __restrict__ ei32) {
    __shared__ int nz;
    if (threadIdx.x == 0) nz = 0;
    __syncthreads();
    int cnt = 0;
    for (int i = threadIdx.x; i < 4096; i += blockDim.x)
        if (ei32[2 * i + 1] != 0) cnt++;
    atomicAdd(&nz, cnt);
    __syncthreads();
    if (threadIdx.x == 0) g_is64 = (nz == 0) ? 1 : 0;
}

// Safe index fetch: branch on detected dtype, clamp to [0, NN) so bad data can
// never produce a wild address (wrong answer > device trap).
__device__ __forceinline__ int fetch_idx(const void* ei, int part, int e) {
    int v;
    if (g_is64) v = (int)((const long long*)ei)[(size_t)part * NE + e];
    else        v = ((const int*)ei)[(size_t)part * NE + e];
    return (v < 0 || v >= NN) ? 0 : v;
}

// ---------------- CSR build ---------------------------------------------------
__global__ void zero_init_kernel() {
    int i = blockIdx.x * blockDim.x + threadIdx.x;
    if (i < NN) { g_degi[i] = 0; g_cur[i] = 0; }
    if (i < NN * 4) g_S[i] = 0.0f;
}

__global__ void count_kernel(const void* __restrict__ ei) {
    int e = blockIdx.x * blockDim.x + threadIdx.x;
    if (e < NE) {
        int c = fetch_idx(ei, 1, e);
        atomicAdd(&g_degi[c], 1);
    }
}

// single-block exclusive scan of g_degi -> g_off
__global__ void scan_kernel() {
    __shared__ int s[1024];
    const int T = 1024;
    const int C = (NN + T - 1) / T;  // 49
    int t = threadIdx.x;
    int base = t * C;
    int sum = 0;
    for (int i = 0; i < C; i++) {
        int idx = base + i;
        if (idx < NN) sum += g_degi[idx];
    }
    s[t] = sum;
    __syncthreads();
    for (int off = 1; off < T; off <<= 1) {
        int v = (t >= off) ? s[t - off] : 0;
        __syncthreads();
        s[t] += v;
        __syncthreads();
    }
    int run = (t == 0) ? 0 : s[t - 1];
    for (int i = 0; i < C; i++) {
        int idx = base + i;
        if (idx < NN) {
            g_off[idx] = run;
            run += g_degi[idx];
        }
    }
    if (t == T - 1) g_off[NN] = run;
}

__global__ void dinv_kernel() {
    int n = blockIdx.x * blockDim.x + threadIdx.x;
    if (n < NN) {
        int d = g_degi[n];
        g_dinv[n] = (d > 0) ? rsqrtf((float)d) : 0.0f;
    }
}

__global__ void fill_kernel(const void* __restrict__ ei) {
    int e = blockIdx.x * blockDim.x + threadIdx.x;
    if (e < NE) {
        int r = fetch_idx(ei, 0, e);
        int c = fetch_idx(ei, 1, e);
        int p = atomicAdd(&g_cur[c], 1);
        int slot = g_off[c] + p;
        if (slot >= 0 && slot < NE) {
            g_row[slot] = r;
            g_nrm[slot] = g_dinv[r] * g_dinv[c];
        }
    }
}

// per-node S[n][j] = sum over incoming edges of norm * ea[:,j]  (layer-invariant)
__global__ void sedge_kernel(const void* __restrict__ ei,
                             const float* __restrict__ ea) {
    int e = blockIdx.x * blockDim.x + threadIdx.x;
    if (e < NE) {
        int r = fetch_idx(ei, 0, e);
        int c = fetch_idx(ei, 1, e);
        float nrm = g_dinv[r] * g_dinv[c];
        float4 v = *(const float4*)(ea + (size_t)e * 4);
        float* s = g_S + (size_t)c * 4;
        atomicAdd(s + 0, nrm * v.x);
        atomicAdd(s + 1, nrm * v.y);
        atomicAdd(s + 2, nrm * v.z);
        atomicAdd(s + 3, nrm * v.w);
    }
}

// ---------------- aggregation: one warp per destination node ------------------
// agg[n] = sum_slots nrm * h[row]  +  fea(S[n])
// fea[j<128] = S3*ew1[j];  fea[j>=128] = S0*ew2[0][..]+S1*ew2[1][..]+S2*ew2[2][..]
__global__ void __launch_bounds__(256) agg_kernel(
    const float* __restrict__ x_ext,  // layer-0 input
    int use_ext,
    const float* __restrict__ ew1,    // [128]  (this layer)
    const float* __restrict__ ew2)    // [3][128] (this layer)
{
    int warp = (blockIdx.x * blockDim.x + threadIdx.x) >> 5;
    int ln = threadIdx.x & 31;
    if (warp >= NN) return;

    const float* hin = use_ext ? x_ext : g_h;

    float acc[8];
#pragma unroll
    for (int k = 0; k < 8; k++) acc[k] = 0.0f;

    int s = g_off[warp];
    int e_end = g_off[warp + 1];
    for (int i = s; i < e_end; i++) {
        int r = g_row[i];
        float nrm = g_nrm[i];
        const float* hr = hin + (size_t)r * HID;
#pragma unroll
        for (int k = 0; k < 8; k++)
            acc[k] = fmaf(nrm, __ldg(hr + ln + 32 * k), acc[k]);
    }

    float4 S = *(const float4*)(g_S + (size_t)warp * 4);
    float* o = g_agg + (size_t)warp * HID;
#pragma unroll
    for (int k = 0; k < 8; k++) {
        int j = ln + 32 * k;
        float fea;
        if (k < 4) {
            fea = S.w * ew1[j];
        } else {
            int jj = j - 128;
            fea = fmaf(S.x, ew2[jj], fmaf(S.y, ew2[128 + jj], S.z * ew2[256 + jj]));
        }
        o[j] = acc[k] + fea;
    }
}

// ---------------- GEMM: g_tmp = relu([hin, g_agg] @ W + b) --------------------
// W: [512, 256] row-major. Rows [0,256) multiply hin, rows [256,512) multiply agg.
__global__ void __launch_bounds__(256) gemm_kernel(
    const float* __restrict__ x_ext,  // layer-0 input
    int use_ext,
    const float* __restrict__ W,      // [512,256]
    const float* __restrict__ bias)   // [256]
{
    __shared__ float As[8][128];
    __shared__ float Bs[8][132];    // pad to reduce bank conflicts
    const int M = NN;
    int tid = threadIdx.x;
    int bx = blockIdx.x;           // 0..1 (N tile)
    int by = blockIdx.y;           // M tile
    int tx = tid & 15;
    int ty = tid >> 4;
    int rowBase = by * 128;

    const float* A1 = use_ext ? x_ext : g_h;

    float acc[8][8];
#pragma unroll
    for (int i = 0; i < 8; i++)
#pragma unroll
        for (int j = 0; j < 8; j++) acc[i][j] = 0.0f;

    int aRow = tid >> 1;           // 0..127
    int aCol = (tid & 1) * 4;      // 0 or 4
    int bRow = tid >> 5;           // 0..7
    int bCol = (tid & 31) * 4;     // 0..124

    for (int phase = 0; phase < 2; ++phase) {
        const float* A = phase ? (const float*)g_agg : A1;
        const float* Wp = W + (size_t)phase * 256 * 256;
        for (int k0 = 0; k0 < 256; k0 += 8) {
            float4 av = make_float4(0.f, 0.f, 0.f, 0.f);
            int ar = rowBase + aRow;
            if (ar < M) av = *(const float4*)(A + (size_t)ar * 256 + k0 + aCol);
            As[aCol + 0][aRow] = av.x;
            As[aCol + 1][aRow] = av.y;
            As[aCol + 2][aRow] = av.z;
            As[aCol + 3][aRow] = av.w;
            float4 bv = *(const float4*)(Wp + (size_t)(k0 + bRow) * 256 + bx * 128 + bCol);
            Bs[bRow][bCol + 0] = bv.x;
            Bs[bRow][bCol + 1] = bv.y;
            Bs[bRow][bCol + 2] = bv.z;
            Bs[bRow][bCol + 3] = bv.w;
            __syncthreads();
#pragma unroll
            for (int k = 0; k < 8; k++) {
                float a[8], b[8];
#pragma unroll
                for (int i = 0; i < 8; i++) a[i] = As[k][ty * 8 + i];
#pragma unroll
                for (int j = 0; j < 8; j++) b[j] = Bs[k][tx * 8 + j];
#pragma unroll
                for (int i = 0; i < 8; i++)
#pragma unroll
                    for (int j = 0; j < 8; j++)
                        acc[i][j] = fmaf(a[i], b[j], acc[i][j]);
            }
            __syncthreads();
        }
    }

#pragma unroll
    for (int i = 0; i < 8; i++) {
        int r = rowBase + ty * 8 + i;
        if (r >= M) continue;
#pragma unroll
        for (int j = 0; j < 8; j += 4) {
            int c = bx * 128 + tx * 8 + j;
            float4 v;
            v.x = fmaxf(acc[i][j + 0] + bias[c + 0], 0.0f);
            v.y = fmaxf(acc[i][j + 1] + bias[c + 1], 0.0f);
            v.z = fmaxf(acc[i][j + 2] + bias[c + 2], 0.0f);
            v.w = fmaxf(acc[i][j + 3] + bias[c + 3], 0.0f);
            *(float4*)(g_tmp + (size_t)r * 256 + c) = v;
        }
    }
}

// ---------------- BatchNorm ---------------------------------------------------
__global__ void zero_stats_kernel() {
    int t = threadIdx.x;
    if (t < HID) g_cs[t] = 0.0f;
    else if (t < 2 * HID) g_cs2[t - HID] = 0.0f;
}

__global__ void __launch_bounds__(256) bnstat_kernel() {
    int c = threadIdx.x;           // column
    int r0 = blockIdx.x * 128;
    int r1 = min(r0 + 128, NN);
    float s = 0.0f, s2 = 0.0f;
    for (int r = r0; r < r1; r++) {
        float v = g_tmp[(size_t)r * HID + c];
        s += v;
        s2 += v * v;
    }
    atomicAdd(&g_cs[c], s);
    atomicAdd(&g_cs2[c], s2);
}

__global__ void __launch_bounds__(256) bnapply_kernel(
    float* __restrict__ out_ext, int use_ext,
    const float* __restrict__ gamma, const float* __restrict__ beta, int dorelu)
{
    int idx = blockIdx.x * blockDim.x + threadIdx.x;
    if (idx >= NN * HID) return;
    float* O = use_ext ? out_ext : g_h;
    int c = idx & (HID - 1);
    const float invn = 1.0f / (float)NN;
    float mu = g_cs[c] * invn;
    float var = g_cs2[c] * invn - mu * mu;
    float sc = rsqrtf(var + BN_EPS) * gamma[c];
    float v = (g_tmp[idx] - mu) * sc + beta[c];
    if (dorelu) v = fmaxf(v, 0.0f);
    O[idx] = v;
}

// ---------------- launch ------------------------------------------------------
extern "C" void kernel_launch(void* const* d_in, const int* in_sizes, int n_in,
                              void* d_out, int out_size) {
    const float* x     = (const float*)d_in[0];      // [NN,256]
    const void*  ei    = d_in[1];                    // [2,NE] int64 OR int32
    const float* ea    = (const float*)d_in[2];      // [NE,4]
    const float* mlp_w = (const float*)d_in[3];      // [5,512,256]
    const float* mlp_b = (const float*)d_in[4];      // [5,256]
    const float* ew1   = (const float*)d_in[5];      // [5,1,128]
    const float* ew2   = (const float*)d_in[6];      // [5,3,128]
    const float* bn_g  = (const float*)d_in[7];      // [5,256]
    const float* bn_b  = (const float*)d_in[8];      // [5,256]
    float* out = (float*)d_out;

    // dtype detection + CSR build + layer-invariant edge sums
    detect_kernel<<<1, 256>>>((const int*)ei);
    zero_init_kernel<<<(NN * 4 + 255) / 256, 256>>>();
    count_kernel<<<(NE + 255) / 256, 256>>>(ei);
    scan_kernel<<<1, 1024>>>();
    dinv_kernel<<<(NN + 255) / 256, 256>>>();
    fill_kernel<<<(NE + 255) / 256, 256>>>(ei);
    sedge_kernel<<<(NE + 255) / 256, 256>>>(ei, ea);

    for (int l = 0; l < NLAYERS; l++) {
        int first = (l == 0) ? 1 : 0;
        int last  = (l == NLAYERS - 1) ? 1 : 0;

        agg_kernel<<<(NN * 32 + 255) / 256, 256>>>(
            x, first, ew1 + (size_t)l * 128, ew2 + (size_t)l * 3 * 128);

        dim3 ggrid(2, (NN + 127) / 128);
        gemm_kernel<<<ggrid, 256>>>(
            x, first, mlp_w + (size_t)l * 512 * 256, mlp_b + (size_t)l * 256);

        zero_stats_kernel<<<1, 512>>>();
        bnstat_kernel<<<(NN + 127) / 128, 256>>>();
        bnapply_kernel<<<(NN * HID + 255) / 256, 256>>>(
            out, last, bn_g + (size_t)l * 256, bn_b + (size_t)l * 256, last ? 0 : 1);
    }
}